// round 5
// baseline (speedup 1.0000x reference)
#include <cuda_runtime.h>
#include <cuda_bf16.h>

// Problem constants
#define SQ   1024   // sequence length
#define BB   8      // batch
#define HH   1024   // hidden
#define NHD  16     // num heads
#define HDI  64     // head dim

// ---------------------------------------------------------------------------
// Scratch (device globals: no allocation allowed)
// ---------------------------------------------------------------------------
__device__ float g_qp[(size_t)BB * NHD * SQ * HDI];   // [b][h][s][d]
__device__ float g_kp[(size_t)BB * NHD * SQ * HDI];
__device__ float g_vp[(size_t)BB * NHD * SQ * HDI];
__device__ float g_bias[BB * SQ];                     // -1e6 * mask
__device__ int   g_mmode;                             // 0=bool bytes, 1=int32, 2=float32

// ---------------------------------------------------------------------------
// TF32 helpers
// ---------------------------------------------------------------------------
__device__ __forceinline__ unsigned f2tf(float x) {
    unsigned u;
    asm("cvt.rna.tf32.f32 %0, %1;" : "=r"(u) : "f"(x));
    return u;
}

__device__ __forceinline__ void mma8(float c[4], const unsigned a[4], const unsigned b[2]) {
    asm volatile(
        "mma.sync.aligned.m16n8k8.row.col.f32.tf32.tf32.f32 "
        "{%0,%1,%2,%3}, {%4,%5,%6,%7}, {%8,%9}, {%0,%1,%2,%3};"
        : "+f"(c[0]), "+f"(c[1]), "+f"(c[2]), "+f"(c[3])
        : "r"(a[0]), "r"(a[1]), "r"(a[2]), "r"(a[3]),
          "r"(b[0]), "r"(b[1]));
}

// ---------------------------------------------------------------------------
// Mask dtype detection.  Reads only the first 8KB (in-bounds for bool(1B),
// int32, or float32 storage of the 8192-element mask).
//   int32 mask: all words in {0,1}
//   fp32  mask: all words in {0, 0x3F800000}
//   else      : bool bytes
// ---------------------------------------------------------------------------
__global__ void k_detect(const unsigned* __restrict__ m) {
    bool i32 = true, f32 = true;
    for (int i = 0; i < 2048; i++) {
        unsigned v = m[i];
        if (v > 1u) i32 = false;
        if (v != 0u && v != 0x3F800000u) f32 = false;
    }
    g_mmode = i32 ? 1 : (f32 ? 2 : 0);
}

__global__ void k_bias(const void* __restrict__ mask) {
    int i = blockIdx.x * blockDim.x + threadIdx.x;
    if (i >= BB * SQ) return;
    int mode = g_mmode;
    float v;
    if (mode == 1)      v = (float)((const int*)mask)[i];
    else if (mode == 2) v = ((const float*)mask)[i];
    else                v = (float)((const unsigned char*)mask)[i];
    g_bias[i] = v * -1000000.0f;
}

// ---------------------------------------------------------------------------
// Projection GEMM:  Out[b][h][s][d] = X[(s*B+b)] . W[n] + bias[n]
// X is [S,B,H] == row-major [8192,1024] with row m = s*B + b.
// BM=128, BN=64, BK=32, 256 threads = 8 warps (4 x 2), warp tile 32x32.
// ---------------------------------------------------------------------------
__global__ __launch_bounds__(256) void k_proj(const float* __restrict__ X,
                                              const float* __restrict__ W,
                                              const float* __restrict__ bias,
                                              int which)
{
    float* Out = (which == 0) ? g_qp : ((which == 1) ? g_kp : g_vp);

    __shared__ float As[128][33];
    __shared__ float Bs[64][33];

    const int tid  = threadIdx.x;
    const int lane = tid & 31;
    const int warp = tid >> 5;
    const int wm   = warp >> 1;     // 0..3
    const int wn   = warp & 1;      // 0..1
    const int g    = lane >> 2;     // 0..7
    const int t4   = lane & 3;      // 0..3
    const int bm   = blockIdx.y * 128;
    const int bn   = blockIdx.x * 64;

    float acc[2][4][4];
#pragma unroll
    for (int mt = 0; mt < 2; mt++)
#pragma unroll
        for (int nt = 0; nt < 4; nt++)
#pragma unroll
            for (int i = 0; i < 4; i++) acc[mt][nt][i] = 0.0f;

    for (int k0 = 0; k0 < HH; k0 += 32) {
        // A tile: 128 x 32  (1024 float4, 4 per thread)
#pragma unroll
        for (int t = 0; t < 4; t++) {
            int i4 = tid + t * 256;
            int r  = i4 >> 3;
            int c  = (i4 & 7) << 2;
            const float4 v = *reinterpret_cast<const float4*>(
                &X[(size_t)(bm + r) * HH + k0 + c]);
            As[r][c + 0] = v.x; As[r][c + 1] = v.y;
            As[r][c + 2] = v.z; As[r][c + 3] = v.w;
        }
        // B tile: 64 x 32   (512 float4, 2 per thread)
#pragma unroll
        for (int t = 0; t < 2; t++) {
            int i4 = tid + t * 256;
            int r  = i4 >> 3;
            int c  = (i4 & 7) << 2;
            const float4 v = *reinterpret_cast<const float4*>(
                &W[(size_t)(bn + r) * HH + k0 + c]);
            Bs[r][c + 0] = v.x; Bs[r][c + 1] = v.y;
            Bs[r][c + 2] = v.z; Bs[r][c + 3] = v.w;
        }
        __syncthreads();

#pragma unroll
        for (int k8 = 0; k8 < 4; k8++) {
            const int kk = k8 * 8;
            unsigned a[2][4], bf[4][2];
#pragma unroll
            for (int mt = 0; mt < 2; mt++) {
                const int r = wm * 32 + mt * 16;
                a[mt][0] = f2tf(As[r + g][kk + t4]);
                a[mt][1] = f2tf(As[r + g + 8][kk + t4]);
                a[mt][2] = f2tf(As[r + g][kk + t4 + 4]);
                a[mt][3] = f2tf(As[r + g + 8][kk + t4 + 4]);
            }
#pragma unroll
            for (int nt = 0; nt < 4; nt++) {
                const int n = wn * 32 + nt * 8 + g;
                bf[nt][0] = f2tf(Bs[n][kk + t4]);
                bf[nt][1] = f2tf(Bs[n][kk + t4 + 4]);
            }
#pragma unroll
            for (int mt = 0; mt < 2; mt++)
#pragma unroll
                for (int nt = 0; nt < 4; nt++)
                    mma8(acc[mt][nt], a[mt], bf[nt]);
        }
        __syncthreads();
    }

    // Epilogue: add bias, scatter to [b][h][s][d]
#pragma unroll
    for (int mt = 0; mt < 2; mt++) {
        const int r0 = bm + wm * 32 + mt * 16 + g;
#pragma unroll
        for (int nt = 0; nt < 4; nt++) {
            const int n0  = bn + wn * 32 + nt * 8 + t4 * 2;
            const float b0v = bias[n0];
            const float b1v = bias[n0 + 1];
            const int h = n0 >> 6;
            const int d = n0 & 63;
#pragma unroll
            for (int half = 0; half < 2; half++) {
                const int m  = r0 + half * 8;
                const int s  = m >> 3;     // m = s*B + b
                const int bb = m & 7;
                float* o = &Out[(((size_t)bb * NHD + h) * SQ + s) * HDI + d];
                o[0] = acc[mt][nt][half * 2 + 0] + b0v;
                o[1] = acc[mt][nt][half * 2 + 1] + b1v;
            }
        }
    }
}

// ---------------------------------------------------------------------------
// Fused attention: one block per (b, h, 32 q rows).  128 threads = 4 warps.
// smem: P[32][1028] exp-scores (conflict-free tf32 frag loads: stride%32==4),
//       Qs[32][68], KVs[64][68], bias[1024], inv[32].
// ---------------------------------------------------------------------------
#define P_STRIDE 1028
#define QS_OFF   (32 * P_STRIDE)             // 32896
#define KV_OFF   (QS_OFF + 32 * 68)          // 35072
#define BIAS_OFF (KV_OFF + 64 * 68)          // 39424
#define INV_OFF  (BIAS_OFF + 1024)           // 40448
#define ATTN_SMEM_FLOATS (INV_OFF + 32)      // 40480
#define ATTN_SMEM_BYTES  (ATTN_SMEM_FLOATS * 4)

__global__ __launch_bounds__(128) void k_attn(float* __restrict__ ctx,
                                              float* __restrict__ attn)
{
    extern __shared__ float sm[];
    float* P     = sm;
    float* Qs    = sm + QS_OFF;
    float* KVs   = sm + KV_OFF;
    float* sBias = sm + BIAS_OFF;
    float* sInv  = sm + INV_OFF;

    const int tid  = threadIdx.x;
    const int lane = tid & 31;
    const int warp = tid >> 5;
    const int g    = lane >> 2;
    const int t4   = lane & 3;
    const int qt   = blockIdx.x * 32;
    const int h    = blockIdx.y;
    const int b    = blockIdx.z;
    const size_t bh = (size_t)b * NHD + h;

    const float* Qg = g_qp + (bh * SQ + qt) * HDI;
    const float* Kg = g_kp + bh * SQ * HDI;
    const float* Vg = g_vp + bh * SQ * HDI;

    // Load Q tile (32x64) and bias row
#pragma unroll
    for (int t = 0; t < 4; t++) {
        int i4 = tid + t * 128;
        int r  = i4 >> 4;
        int c  = (i4 & 15) << 2;
        float4 v = *reinterpret_cast<const float4*>(&Qg[r * 64 + c]);
        Qs[r * 68 + c + 0] = v.x; Qs[r * 68 + c + 1] = v.y;
        Qs[r * 68 + c + 2] = v.z; Qs[r * 68 + c + 3] = v.w;
    }
    for (int i = tid; i < SQ; i += 128) sBias[i] = g_bias[b * SQ + i];

    // ---- Phase 1: scores -> exp -> P (smem) ----
    for (int kt = 0; kt < 16; kt++) {
        __syncthreads();   // covers Q/bias loads on kt=0; KVs reuse otherwise
#pragma unroll
        for (int t = 0; t < 8; t++) {
            int i4 = tid + t * 128;
            int r  = i4 >> 4;
            int c  = (i4 & 15) << 2;
            float4 v = *reinterpret_cast<const float4*>(&Kg[(kt * 64 + r) * 64 + c]);
            KVs[r * 68 + c + 0] = v.x; KVs[r * 68 + c + 1] = v.y;
            KVs[r * 68 + c + 2] = v.z; KVs[r * 68 + c + 3] = v.w;
        }
        __syncthreads();

        float c_[2][2][4] = {};
#pragma unroll
        for (int k8 = 0; k8 < 8; k8++) {
            const int kk = k8 * 8;
            unsigned a[2][4], bf[2][2];
#pragma unroll
            for (int mt = 0; mt < 2; mt++) {
                const int r = mt * 16;
                a[mt][0] = f2tf(Qs[(r + g) * 68 + kk + t4]);
                a[mt][1] = f2tf(Qs[(r + g + 8) * 68 + kk + t4]);
                a[mt][2] = f2tf(Qs[(r + g) * 68 + kk + t4 + 4]);
                a[mt][3] = f2tf(Qs[(r + g + 8) * 68 + kk + t4 + 4]);
            }
#pragma unroll
            for (int nt = 0; nt < 2; nt++) {
                const int n = warp * 16 + nt * 8 + g;
                bf[nt][0] = f2tf(KVs[n * 68 + kk + t4]);
                bf[nt][1] = f2tf(KVs[n * 68 + kk + t4 + 4]);
            }
#pragma unroll
            for (int mt = 0; mt < 2; mt++)
#pragma unroll
                for (int nt = 0; nt < 2; nt++)
                    mma8(c_[mt][nt], a[mt], bf[nt]);
        }
        // scale, mask-bias, exp, store
#pragma unroll
        for (int mt = 0; mt < 2; mt++)
#pragma unroll
            for (int nt = 0; nt < 2; nt++)
#pragma unroll
                for (int i = 0; i < 4; i++) {
                    int row = mt * 16 + g + ((i >> 1) << 3);
                    int key = kt * 64 + warp * 16 + nt * 8 + t4 * 2 + (i & 1);
                    float pv = __expf(c_[mt][nt][i] * 0.125f + sBias[key]);
                    P[row * P_STRIDE + key] = pv;
                }
    }
    __syncthreads();

    // ---- Phase 2: row sums -> 1/sum ----
#pragma unroll
    for (int i = 0; i < 8; i++) {
        int row = warp * 8 + i;
        float ssum = 0.0f;
        for (int c = lane; c < SQ; c += 32) ssum += P[row * P_STRIDE + c];
#pragma unroll
        for (int o = 16; o; o >>= 1) ssum += __shfl_xor_sync(0xffffffffu, ssum, o);
        if (lane == 0) sInv[row] = 1.0f / ssum;
    }
    __syncthreads();

    // ---- Phase 3: normalize in smem + write attn weights ----
    float* attn_base = attn + (bh * SQ + qt) * SQ;
#pragma unroll 4
    for (int t = 0; t < 64; t++) {
        int i4 = tid + t * 128;            // 0..8191 (32 rows x 256 float4)
        int r  = i4 >> 8;
        int c  = (i4 & 255) << 2;
        float inv = sInv[r];
        float4 v = *reinterpret_cast<float4*>(&P[r * P_STRIDE + c]);
        v.x *= inv; v.y *= inv; v.z *= inv; v.w *= inv;
        *reinterpret_cast<float4*>(&P[r * P_STRIDE + c]) = v;
        *reinterpret_cast<float4*>(&attn_base[(size_t)r * SQ + c]) = v;
    }

    // ---- Phase 4: O = P @ V ----
    float o_[2][2][4] = {};
    for (int kt = 0; kt < 16; kt++) {
        __syncthreads();
#pragma unroll
        for (int t = 0; t < 8; t++) {
            int i4 = tid + t * 128;
            int r  = i4 >> 4;
            int c  = (i4 & 15) << 2;
            float4 v = *reinterpret_cast<const float4*>(&Vg[(kt * 64 + r) * 64 + c]);
            KVs[r * 68 + c + 0] = v.x; KVs[r * 68 + c + 1] = v.y;
            KVs[r * 68 + c + 2] = v.z; KVs[r * 68 + c + 3] = v.w;
        }
        __syncthreads();
#pragma unroll
        for (int k8 = 0; k8 < 8; k8++) {
            const int kk  = kt * 64 + k8 * 8;   // global key index for P
            const int kkl = k8 * 8;             // local k row in V tile
            unsigned a[2][4], bf[2][2];
#pragma unroll
            for (int mt = 0; mt < 2; mt++) {
                const int r = mt * 16;
                a[mt][0] = f2tf(P[(r + g) * P_STRIDE + kk + t4]);
                a[mt][1] = f2tf(P[(r + g + 8) * P_STRIDE + kk + t4]);
                a[mt][2] = f2tf(P[(r + g) * P_STRIDE + kk + t4 + 4]);
                a[mt][3] = f2tf(P[(r + g + 8) * P_STRIDE + kk + t4 + 4]);
            }
#pragma unroll
            for (int nt = 0; nt < 2; nt++) {
                const int n = warp * 16 + nt * 8 + g;   // head-dim column
                bf[nt][0] = f2tf(KVs[(kkl + t4) * 68 + n]);
                bf[nt][1] = f2tf(KVs[(kkl + t4 + 4) * 68 + n]);
            }
#pragma unroll
            for (int mt = 0; mt < 2; mt++)
#pragma unroll
                for (int nt = 0; nt < 2; nt++)
                    mma8(o_[mt][nt], a[mt], bf[nt]);
        }
    }

    // ---- Epilogue: ctx[s][b][h*64+d] ----
#pragma unroll
    for (int mt = 0; mt < 2; mt++)
#pragma unroll
        for (int nt = 0; nt < 2; nt++)
#pragma unroll
            for (int i = 0; i < 4; i++) {
                int row = mt * 16 + g + ((i >> 1) << 3);
                int s   = qt + row;
                int d   = warp * 16 + nt * 8 + t4 * 2 + (i & 1);
                ctx[((size_t)s * BB + b) * HH + h * HDI + d] = o_[mt][nt][i];
            }
}

// ---------------------------------------------------------------------------
// Launch
// ---------------------------------------------------------------------------
extern "C" void kernel_launch(void* const* d_in, const int* in_sizes, int n_in,
                              void* d_out, int out_size)
{
    const float* q    = (const float*)d_in[0];
    const float* k    = (const float*)d_in[1];
    const float* v    = (const float*)d_in[2];
    const void*  mask = d_in[3];
    const float* Wq   = (const float*)d_in[4];
    const float* bq   = (const float*)d_in[5];
    const float* Wk   = (const float*)d_in[6];
    const float* bk   = (const float*)d_in[7];
    const float* Wv   = (const float*)d_in[8];
    const float* bv   = (const float*)d_in[9];

    float* out  = (float*)d_out;
    float* ctx  = out;                               // [S,B,H]
    float* attn = out + (size_t)SQ * BB * HH;        // [B,NH,S,S]

    k_detect<<<1, 1>>>((const unsigned*)mask);
    k_bias<<<(BB * SQ + 255) / 256, 256>>>(mask);

    dim3 pgrid(HH / 64, (BB * SQ) / 128);
    k_proj<<<pgrid, 256>>>(q, Wq, bq, 0);
    k_proj<<<pgrid, 256>>>(k, Wk, bk, 1);
    k_proj<<<pgrid, 256>>>(v, Wv, bv, 2);

    cudaFuncSetAttribute(k_attn, cudaFuncAttributeMaxDynamicSharedMemorySize,
                         ATTN_SMEM_BYTES);
    k_attn<<<dim3(SQ / 32, NHD, BB), 128, ATTN_SMEM_BYTES>>>(ctx, attn);
}

// round 6
// speedup vs baseline: 2.2933x; 2.2933x over previous
#include <cuda_runtime.h>
#include <cuda_bf16.h>

// Problem constants
#define SQ   1024   // sequence length
#define BB   8      // batch
#define HH   1024   // hidden
#define NHD  16     // num heads
#define HDI  64     // head dim

// ---------------------------------------------------------------------------
// Scratch (device globals: no allocation allowed)
// ---------------------------------------------------------------------------
__device__ float g_qp[(size_t)BB * NHD * SQ * HDI];   // [b][h][s][d]
__device__ float g_kp[(size_t)BB * NHD * SQ * HDI];
__device__ float g_vp[(size_t)BB * NHD * SQ * HDI];
__device__ float g_bias[BB * SQ];                     // -1e6 * mask
__device__ float g_psum[(size_t)BB * NHD * SQ * 8];   // partial row sums (per k-block)
__device__ float g_rinv[(size_t)BB * NHD * SQ];       // 1 / rowsum
__device__ int   g_mmode;

// ---------------------------------------------------------------------------
// TF32 helpers
// ---------------------------------------------------------------------------
__device__ __forceinline__ unsigned f2tf(float x) {
    unsigned u;
    asm("cvt.rna.tf32.f32 %0, %1;" : "=r"(u) : "f"(x));
    return u;
}
__device__ __forceinline__ uint4 f2tf4(float4 v) {
    return make_uint4(f2tf(v.x), f2tf(v.y), f2tf(v.z), f2tf(v.w));
}
__device__ __forceinline__ void mma8(float c[4], const unsigned a[4], const unsigned b[2]) {
    asm volatile(
        "mma.sync.aligned.m16n8k8.row.col.f32.tf32.tf32.f32 "
        "{%0,%1,%2,%3}, {%4,%5,%6,%7}, {%8,%9}, {%0,%1,%2,%3};"
        : "+f"(c[0]), "+f"(c[1]), "+f"(c[2]), "+f"(c[3])
        : "r"(a[0]), "r"(a[1]), "r"(a[2]), "r"(a[3]),
          "r"(b[0]), "r"(b[1]));
}

// ---------------------------------------------------------------------------
// Mask dtype detection + bias build (unchanged from passing R4 kernel)
// ---------------------------------------------------------------------------
__global__ void k_detect(const unsigned* __restrict__ m) {
    bool i32 = true, f32 = true;
    for (int i = 0; i < 2048; i++) {
        unsigned v = m[i];
        if (v > 1u) i32 = false;
        if (v != 0u && v != 0x3F800000u) f32 = false;
    }
    g_mmode = i32 ? 1 : (f32 ? 2 : 0);
}
__global__ void k_bias(const void* __restrict__ mask) {
    int i = blockIdx.x * blockDim.x + threadIdx.x;
    if (i >= BB * SQ) return;
    int mode = g_mmode;
    float v;
    if (mode == 1)      v = (float)((const int*)mask)[i];
    else if (mode == 2) v = ((const float*)mask)[i];
    else                v = (float)((const unsigned char*)mask)[i];
    g_bias[i] = v * -1000000.0f;
}

// ---------------------------------------------------------------------------
// Projection GEMM (all 3 in one launch, blockIdx.z selects which):
//   Out[b][h][s][d] = X[m=s*B+b] . W[n] + bias[n]
// BM=128, BN=128, BK=32, 256 thr = 8 warps (2 x 4), warp tile 64x32.
// TF32 pre-converted in smem; pad stride 36 (36%32==4 -> conflict-free frags).
// ---------------------------------------------------------------------------
__global__ __launch_bounds__(256) void k_proj(
    const float* __restrict__ Xq, const float* __restrict__ Xk, const float* __restrict__ Xv,
    const float* __restrict__ Wq, const float* __restrict__ bq,
    const float* __restrict__ Wk, const float* __restrict__ bk,
    const float* __restrict__ Wv, const float* __restrict__ bv)
{
    const int which = blockIdx.z;
    const float* X    = (which == 0) ? Xq : ((which == 1) ? Xk : Xv);
    const float* W    = (which == 0) ? Wq : ((which == 1) ? Wk : Wv);
    const float* bias = (which == 0) ? bq : ((which == 1) ? bk : bv);
    float* Out        = (which == 0) ? g_qp : ((which == 1) ? g_kp : g_vp);

    __shared__ unsigned As[128][36];
    __shared__ unsigned Bs[128][36];

    const int tid  = threadIdx.x;
    const int lane = tid & 31;
    const int warp = tid >> 5;
    const int wm   = warp >> 2;     // 0..1
    const int wn   = warp & 3;      // 0..3
    const int g    = lane >> 2;
    const int t4   = lane & 3;
    const int bm   = blockIdx.y * 128;
    const int bn   = blockIdx.x * 128;

    float acc[4][4][4];
#pragma unroll
    for (int mt = 0; mt < 4; mt++)
#pragma unroll
        for (int nt = 0; nt < 4; nt++)
#pragma unroll
            for (int i = 0; i < 4; i++) acc[mt][nt][i] = 0.0f;

    for (int k0 = 0; k0 < HH; k0 += 32) {
#pragma unroll
        for (int t = 0; t < 4; t++) {
            int i4 = tid + t * 256;
            int r  = i4 >> 3;
            int c  = (i4 & 7) << 2;
            float4 a4 = *reinterpret_cast<const float4*>(&X[(size_t)(bm + r) * HH + k0 + c]);
            *reinterpret_cast<uint4*>(&As[r][c]) = f2tf4(a4);
            float4 b4 = *reinterpret_cast<const float4*>(&W[(size_t)(bn + r) * HH + k0 + c]);
            *reinterpret_cast<uint4*>(&Bs[r][c]) = f2tf4(b4);
        }
        __syncthreads();

#pragma unroll
        for (int k8 = 0; k8 < 4; k8++) {
            const int kk = k8 * 8;
            unsigned a[4][4], bf[4][2];
#pragma unroll
            for (int mt = 0; mt < 4; mt++) {
                const int r = wm * 64 + mt * 16;
                a[mt][0] = As[r + g][kk + t4];
                a[mt][1] = As[r + g + 8][kk + t4];
                a[mt][2] = As[r + g][kk + t4 + 4];
                a[mt][3] = As[r + g + 8][kk + t4 + 4];
            }
#pragma unroll
            for (int nt = 0; nt < 4; nt++) {
                const int n = wn * 32 + nt * 8 + g;
                bf[nt][0] = Bs[n][kk + t4];
                bf[nt][1] = Bs[n][kk + t4 + 4];
            }
#pragma unroll
            for (int mt = 0; mt < 4; mt++)
#pragma unroll
                for (int nt = 0; nt < 4; nt++)
                    mma8(acc[mt][nt], a[mt], bf[nt]);
        }
        __syncthreads();
    }

    // Epilogue: add bias, scatter to [b][h][s][d]
#pragma unroll
    for (int mt = 0; mt < 4; mt++) {
        const int r0 = bm + wm * 64 + mt * 16 + g;
#pragma unroll
        for (int nt = 0; nt < 4; nt++) {
            const int n0  = bn + wn * 32 + nt * 8 + t4 * 2;
            const float b0v = bias[n0];
            const float b1v = bias[n0 + 1];
            const int h = n0 >> 6;
            const int d = n0 & 63;
#pragma unroll
            for (int half = 0; half < 2; half++) {
                const int m  = r0 + half * 8;
                const int s  = m >> 3;     // m = s*B + b
                const int bb = m & 7;
                float2 val = make_float2(acc[mt][nt][half * 2 + 0] + b0v,
                                         acc[mt][nt][half * 2 + 1] + b1v);
                *reinterpret_cast<float2*>(
                    &Out[(((size_t)bb * NHD + h) * SQ + s) * HDI + d]) = val;
            }
        }
    }
}

// ---------------------------------------------------------------------------
// Kernel A: exp-scores.  Block = 128q x 128k for one (b,h).  256 thr, 8 warps
// (2 x 4), warp tile 64x32.  K=64 single pass.  Writes unnormalized exp scores
// to attn and deterministic partial row sums to g_psum[bh][q][kblk].
// smem: Qs[128][68]u, Ks[128][68]u, bias[128], sums[128][4]
// ---------------------------------------------------------------------------
#define A_SMEM_FLOATS (128 * 68 * 2 + 128 + 128 * 4)
#define A_SMEM_BYTES  (A_SMEM_FLOATS * 4)

__global__ __launch_bounds__(256) void k_scores(float* __restrict__ attn)
{
    extern __shared__ float sm[];
    unsigned* Qs   = (unsigned*)sm;
    unsigned* Ks   = Qs + 128 * 68;
    float*    sBias = (float*)(Ks + 128 * 68);
    float*    sSum  = sBias + 128;

    const int tid  = threadIdx.x;
    const int lane = tid & 31;
    const int warp = tid >> 5;
    const int g    = lane >> 2;
    const int t4   = lane & 3;
    const int kb   = blockIdx.x;
    const int qb   = blockIdx.y;
    const int bh   = blockIdx.z;
    const int b    = bh >> 4;

    const float* Qg = g_qp + ((size_t)bh * SQ + qb * 128) * HDI;
    const float* Kg = g_kp + ((size_t)bh * SQ + kb * 128) * HDI;

#pragma unroll
    for (int t = 0; t < 8; t++) {
        int i4 = tid + t * 256;
        int r  = i4 >> 4;
        int c  = (i4 & 15) << 2;
        float4 q4 = *reinterpret_cast<const float4*>(&Qg[r * 64 + c]);
        *reinterpret_cast<uint4*>(&Qs[r * 68 + c]) = f2tf4(q4);
        float4 k4 = *reinterpret_cast<const float4*>(&Kg[r * 64 + c]);
        *reinterpret_cast<uint4*>(&Ks[r * 68 + c]) = f2tf4(k4);
    }
    if (tid < 128) sBias[tid] = g_bias[b * SQ + kb * 128 + tid];
    __syncthreads();

    const int wm = warp >> 2;   // 0..1
    const int wn = warp & 3;    // 0..3

    float acc[4][4][4];
#pragma unroll
    for (int mt = 0; mt < 4; mt++)
#pragma unroll
        for (int nt = 0; nt < 4; nt++)
#pragma unroll
            for (int i = 0; i < 4; i++) acc[mt][nt][i] = 0.0f;

#pragma unroll
    for (int k8 = 0; k8 < 8; k8++) {
        const int kk = k8 * 8;
        unsigned a[4][4], bf[4][2];
#pragma unroll
        for (int mt = 0; mt < 4; mt++) {
            const int r = wm * 64 + mt * 16;
            a[mt][0] = Qs[(r + g) * 68 + kk + t4];
            a[mt][1] = Qs[(r + g + 8) * 68 + kk + t4];
            a[mt][2] = Qs[(r + g) * 68 + kk + t4 + 4];
            a[mt][3] = Qs[(r + g + 8) * 68 + kk + t4 + 4];
        }
#pragma unroll
        for (int nt = 0; nt < 4; nt++) {
            const int n = wn * 32 + nt * 8 + g;
            bf[nt][0] = Ks[n * 68 + kk + t4];
            bf[nt][1] = Ks[n * 68 + kk + t4 + 4];
        }
#pragma unroll
        for (int mt = 0; mt < 4; mt++)
#pragma unroll
            for (int nt = 0; nt < 4; nt++)
                mma8(acc[mt][nt], a[mt], bf[nt]);
    }

    float* attn_base = attn + ((size_t)bh * SQ + qb * 128) * SQ + kb * 128;
#pragma unroll
    for (int mt = 0; mt < 4; mt++) {
#pragma unroll
        for (int half = 0; half < 2; half++) {
            const int rl = wm * 64 + mt * 16 + g + half * 8;
            float rs = 0.0f;
#pragma unroll
            for (int nt = 0; nt < 4; nt++) {
                const int cl = wn * 32 + nt * 8 + t4 * 2;
                float p0 = __expf(acc[mt][nt][half * 2 + 0] * 0.125f + sBias[cl]);
                float p1 = __expf(acc[mt][nt][half * 2 + 1] * 0.125f + sBias[cl + 1]);
                *reinterpret_cast<float2*>(&attn_base[(size_t)rl * SQ + cl]) =
                    make_float2(p0, p1);
                rs += p0 + p1;
            }
            rs += __shfl_xor_sync(0xffffffffu, rs, 1);
            rs += __shfl_xor_sync(0xffffffffu, rs, 2);
            if (t4 == 0) sSum[rl * 4 + wn] = rs;
        }
    }
    __syncthreads();
    if (tid < 128) {
        float s = sSum[tid * 4] + sSum[tid * 4 + 1] + sSum[tid * 4 + 2] + sSum[tid * 4 + 3];
        g_psum[((size_t)bh * SQ + qb * 128 + tid) * 8 + kb] = s;
    }
}

// ---------------------------------------------------------------------------
// Reduce partial sums -> 1/rowsum (deterministic, no atomics)
// ---------------------------------------------------------------------------
__global__ void k_rsum() {
    int i = blockIdx.x * blockDim.x + threadIdx.x;
    if (i >= BB * NHD * SQ) return;
    const float* p = &g_psum[(size_t)i * 8];
    float s = ((p[0] + p[1]) + (p[2] + p[3])) + ((p[4] + p[5]) + (p[6] + p[7]));
    g_rinv[i] = 1.0f / s;
}

// ---------------------------------------------------------------------------
// Kernel B: normalize attn in-place + ctx = P @ V.
// Block = 128q x 64d for one (b,h); loops over 8 key tiles of 128.
// 256 thr, 8 warps (4 x 2), warp tile 32x32.
// smem: Ps[128][132]u (132%32==4), Vs[128][72]u (72%32==8 -> b-frag conflict-free),
//       sInv[128]
// ---------------------------------------------------------------------------
#define B_PS  (128 * 132)
#define B_VS  (128 * 72)
#define B_SMEM_FLOATS (B_PS + B_VS + 128)
#define B_SMEM_BYTES  (B_SMEM_FLOATS * 4)

__global__ __launch_bounds__(256) void k_pv(float* __restrict__ attn,
                                            float* __restrict__ ctx)
{
    extern __shared__ float sm[];
    unsigned* Ps  = (unsigned*)sm;
    unsigned* Vs  = Ps + B_PS;
    float*    sInv = (float*)(Vs + B_VS);

    const int tid  = threadIdx.x;
    const int lane = tid & 31;
    const int warp = tid >> 5;
    const int g    = lane >> 2;
    const int t4   = lane & 3;
    const int qb   = blockIdx.x;
    const int bh   = blockIdx.y;
    const int b    = bh >> 4;
    const int h    = bh & 15;

    if (tid < 128) sInv[tid] = g_rinv[(size_t)bh * SQ + qb * 128 + tid];
    __syncthreads();

    float* attn_base = attn + ((size_t)bh * SQ + qb * 128) * SQ;
    const float* Vg  = g_vp + (size_t)bh * SQ * HDI;

    const int wm = warp >> 1;   // 0..3
    const int wn = warp & 1;    // 0..1

    float o[2][4][4];
#pragma unroll
    for (int mt = 0; mt < 2; mt++)
#pragma unroll
        for (int nt = 0; nt < 4; nt++)
#pragma unroll
            for (int i = 0; i < 4; i++) o[mt][nt][i] = 0.0f;

    for (int kt = 0; kt < 8; kt++) {
        // P tile: read unnormalized, scale, write back normalized, stage tf32
#pragma unroll
        for (int t = 0; t < 16; t++) {
            int i4 = tid + t * 256;
            int r  = i4 >> 5;
            int c  = (i4 & 31) << 2;
            float4 p = *reinterpret_cast<const float4*>(
                &attn_base[(size_t)r * SQ + kt * 128 + c]);
            float inv = sInv[r];
            p.x *= inv; p.y *= inv; p.z *= inv; p.w *= inv;
            *reinterpret_cast<float4*>(&attn_base[(size_t)r * SQ + kt * 128 + c]) = p;
            *reinterpret_cast<uint4*>(&Ps[r * 132 + c]) = f2tf4(p);
        }
        // V tile 128x64
#pragma unroll
        for (int t = 0; t < 8; t++) {
            int i4 = tid + t * 256;
            int r  = i4 >> 4;
            int c  = (i4 & 15) << 2;
            float4 v = *reinterpret_cast<const float4*>(&Vg[(size_t)(kt * 128 + r) * 64 + c]);
            *reinterpret_cast<uint4*>(&Vs[r * 72 + c]) = f2tf4(v);
        }
        __syncthreads();

#pragma unroll
        for (int k8 = 0; k8 < 16; k8++) {
            const int kk = k8 * 8;
            unsigned a[2][4], bf[4][2];
#pragma unroll
            for (int mt = 0; mt < 2; mt++) {
                const int r = wm * 32 + mt * 16;
                a[mt][0] = Ps[(r + g) * 132 + kk + t4];
                a[mt][1] = Ps[(r + g + 8) * 132 + kk + t4];
                a[mt][2] = Ps[(r + g) * 132 + kk + t4 + 4];
                a[mt][3] = Ps[(r + g + 8) * 132 + kk + t4 + 4];
            }
#pragma unroll
            for (int nt = 0; nt < 4; nt++) {
                const int n = wn * 32 + nt * 8 + g;   // head-dim column
                bf[nt][0] = Vs[(kk + t4) * 72 + n];
                bf[nt][1] = Vs[(kk + t4 + 4) * 72 + n];
            }
#pragma unroll
            for (int mt = 0; mt < 2; mt++)
#pragma unroll
                for (int nt = 0; nt < 4; nt++)
                    mma8(o[mt][nt], a[mt], bf[nt]);
        }
        __syncthreads();
    }

    // Epilogue: ctx[s][b][h*64+d]
#pragma unroll
    for (int mt = 0; mt < 2; mt++)
#pragma unroll
        for (int nt = 0; nt < 4; nt++)
#pragma unroll
            for (int half = 0; half < 2; half++) {
                int row = wm * 32 + mt * 16 + g + half * 8;
                int s   = qb * 128 + row;
                int d   = wn * 32 + nt * 8 + t4 * 2;
                float2 val = make_float2(o[mt][nt][half * 2 + 0],
                                         o[mt][nt][half * 2 + 1]);
                *reinterpret_cast<float2*>(
                    &ctx[((size_t)s * BB + b) * HH + h * HDI + d]) = val;
            }
}

// ---------------------------------------------------------------------------
// Launch
// ---------------------------------------------------------------------------
extern "C" void kernel_launch(void* const* d_in, const int* in_sizes, int n_in,
                              void* d_out, int out_size)
{
    const float* q    = (const float*)d_in[0];
    const float* k    = (const float*)d_in[1];
    const float* v    = (const float*)d_in[2];
    const void*  mask = d_in[3];
    const float* Wq   = (const float*)d_in[4];
    const float* bq   = (const float*)d_in[5];
    const float* Wk   = (const float*)d_in[6];
    const float* bk   = (const float*)d_in[7];
    const float* Wv   = (const float*)d_in[8];
    const float* bv   = (const float*)d_in[9];

    float* out  = (float*)d_out;
    float* ctx  = out;                               // [S,B,H]
    float* attn = out + (size_t)SQ * BB * HH;        // [B,NH,S,S]

    k_detect<<<1, 1>>>((const unsigned*)mask);
    k_bias<<<(BB * SQ + 255) / 256, 256>>>(mask);

    // All three projections in one launch
    k_proj<<<dim3(HH / 128, (BB * SQ) / 128, 3), 256>>>(
        q, k, v, Wq, bq, Wk, bk, Wv, bv);

    cudaFuncSetAttribute(k_scores, cudaFuncAttributeMaxDynamicSharedMemorySize,
                         A_SMEM_BYTES);
    k_scores<<<dim3(SQ / 128, SQ / 128, BB * NHD), 256, A_SMEM_BYTES>>>(attn);

    k_rsum<<<(BB * NHD * SQ + 255) / 256, 256>>>();

    cudaFuncSetAttribute(k_pv, cudaFuncAttributeMaxDynamicSharedMemorySize,
                         B_SMEM_BYTES);
    k_pv<<<dim3(SQ / 128, BB * NHD), 256, B_SMEM_BYTES>>>(attn, ctx);
}